// round 1
// baseline (speedup 1.0000x reference)
#include <cuda_runtime.h>
#include <mma.h>
#include <cstdint>
#include <cmath>

using namespace nvcuda;

// ---------------- problem dims ----------------
constexpr int Bb = 4, Tt = 4096, SD = 256, Cc = 1024, Aa = 64, Ll = 6, Hh = 16, BSz = 64;
constexpr int Mm = Bb * Tt;          // 16384 rows
constexpr int HD = Cc / Hh;          // 64
constexpr float ATT_SCALE = 0.125f;  // 1/sqrt(64)
constexpr float LN_EPS = 1e-5f;

// ---------------- scratch (device globals; no allocation allowed) ----------------
__device__ float g_x[(size_t)Mm * Cc];            // residual stream
__device__ float g_h[(size_t)Mm * Cc];            // LN output
__device__ float g_qkv[(size_t)Mm * 3 * Cc];      // qkv
__device__ float g_ctx[(size_t)Mm * Cc];          // attention context
__device__ float g_mlp[(size_t)Mm * 4 * Cc];      // mlp hidden

// ---------------- tf32 GEMM: out = EPI(A[M,K] @ W[K,N] + bias) ----------------
// EPI: 0 = +bias; 1 = gelu(+bias); 2 = +bias + aux[row*N+col] (residual);
//      3 = +bias + aux[(row % T)*N + col] (positional embed)
constexpr int BM = 128, BN = 128, BK = 32;

__device__ __forceinline__ float gelu_exact(float x) {
    return 0.5f * x * (1.0f + erff(x * 0.70710678118654752f));
}

template <int EPI>
__global__ __launch_bounds__(256)
void gemm_tf32_kernel(const float* __restrict__ A, const float* __restrict__ Bw,
                      const float* __restrict__ bias, const float* __restrict__ aux,
                      float* __restrict__ out, int M, int N, int K)
{
    __shared__ float As[BM][BK + 4];     // 18.4 KB
    __shared__ float Bs[BK][BN + 4];     // 16.9 KB
    __shared__ float stage[8][16][20];   // 10.2 KB epilogue staging (ldm=20, mult of 4)

    const int tid = threadIdx.x;
    const int w = tid >> 5, lane = tid & 31;
    const int warpM = w >> 2, warpN = w & 3;           // 2 x 4 warps
    const int m0 = blockIdx.y * BM, n0 = blockIdx.x * BN;

    wmma::fragment<wmma::accumulator, 16, 16, 8, float> acc[4][2];
#pragma unroll
    for (int i = 0; i < 4; i++)
#pragma unroll
        for (int j = 0; j < 2; j++) wmma::fill_fragment(acc[i][j], 0.0f);

    int aRow[4], aC4[4], bRow[4], bC4[4];
#pragma unroll
    for (int i = 0; i < 4; i++) {
        int lin = tid + i * 256;
        aRow[i] = lin >> 3;  aC4[i] = lin & 7;    // 128 rows x 8 float4
        bRow[i] = lin >> 5;  bC4[i] = lin & 31;   // 32 rows x 32 float4
    }

    const int nk = K / BK;
    float4 ra[4], rb[4];

#pragma unroll
    for (int i = 0; i < 4; i++) {
        ra[i] = *(const float4*)(A + (size_t)(m0 + aRow[i]) * K + aC4[i] * 4);
        int col = n0 + bC4[i] * 4;
        rb[i] = (col < N) ? *(const float4*)(Bw + (size_t)bRow[i] * N + col)
                          : make_float4(0.f, 0.f, 0.f, 0.f);
    }

    for (int kt = 0; kt < nk; kt++) {
        // store current tile to smem with round-to-nearest tf32 conversion
#pragma unroll
        for (int i = 0; i < 4; i++) {
            float* pa = &As[aRow[i]][aC4[i] * 4];
            pa[0] = wmma::__float_to_tf32(ra[i].x);
            pa[1] = wmma::__float_to_tf32(ra[i].y);
            pa[2] = wmma::__float_to_tf32(ra[i].z);
            pa[3] = wmma::__float_to_tf32(ra[i].w);
            float* pb = &Bs[bRow[i]][bC4[i] * 4];
            pb[0] = wmma::__float_to_tf32(rb[i].x);
            pb[1] = wmma::__float_to_tf32(rb[i].y);
            pb[2] = wmma::__float_to_tf32(rb[i].z);
            pb[3] = wmma::__float_to_tf32(rb[i].w);
        }
        __syncthreads();

        if (kt + 1 < nk) {  // prefetch next tile into registers
            int kbase = (kt + 1) * BK;
#pragma unroll
            for (int i = 0; i < 4; i++) {
                ra[i] = *(const float4*)(A + (size_t)(m0 + aRow[i]) * K + kbase + aC4[i] * 4);
                int col = n0 + bC4[i] * 4;
                rb[i] = (col < N) ? *(const float4*)(Bw + (size_t)(kbase + bRow[i]) * N + col)
                                  : make_float4(0.f, 0.f, 0.f, 0.f);
            }
        }

#pragma unroll
        for (int kk = 0; kk < BK; kk += 8) {
            wmma::fragment<wmma::matrix_b, 16, 16, 8, wmma::precision::tf32, wmma::row_major> bf[2];
#pragma unroll
            for (int in = 0; in < 2; in++)
                wmma::load_matrix_sync(bf[in], &Bs[kk][warpN * 32 + in * 16], BN + 4);
#pragma unroll
            for (int im = 0; im < 4; im++) {
                wmma::fragment<wmma::matrix_a, 16, 16, 8, wmma::precision::tf32, wmma::row_major> af;
                wmma::load_matrix_sync(af, &As[warpM * 64 + im * 16][kk], BK + 4);
#pragma unroll
                for (int in = 0; in < 2; in++)
                    wmma::mma_sync(acc[im][in], af, bf[in], acc[im][in]);
            }
        }
        __syncthreads();
    }

    // epilogue: stage each 16x16 fragment through smem, apply bias/activation
#pragma unroll
    for (int im = 0; im < 4; im++) {
#pragma unroll
        for (int in = 0; in < 2; in++) {
            wmma::store_matrix_sync(&stage[w][0][0], acc[im][in], 20, wmma::mem_row_major);
            __syncwarp();
            int rbase = m0 + warpM * 64 + im * 16;
            int cbase = n0 + warpN * 32 + in * 16;
#pragma unroll
            for (int e = 0; e < 8; e++) {
                int idx = lane + e * 32;
                int r = idx >> 4, c = idx & 15;
                int col = cbase + c;
                if (col < N) {
                    size_t o = (size_t)(rbase + r) * N + col;
                    float v = stage[w][r][c] + bias[col];
                    if (EPI == 1) v = gelu_exact(v);
                    else if (EPI == 2) v += aux[o];
                    else if (EPI == 3) v += aux[(size_t)((rbase + r) & (Tt - 1)) * N + col];
                    out[o] = v;
                }
            }
            __syncwarp();
        }
    }
}

// ---------------- LayerNorm: one block per row of C=1024 ----------------
__global__ __launch_bounds__(256)
void ln_kernel(const float* __restrict__ x, const float* __restrict__ w,
               const float* __restrict__ b, float* __restrict__ o)
{
    int row = blockIdx.x;
    const float* xr = x + (size_t)row * Cc;
    float v[4];
    float s = 0.f, ss = 0.f;
#pragma unroll
    for (int i = 0; i < 4; i++) {
        v[i] = xr[threadIdx.x + i * 256];
        s += v[i]; ss += v[i] * v[i];
    }
#pragma unroll
    for (int off = 16; off; off >>= 1) {
        s  += __shfl_xor_sync(~0u, s, off);
        ss += __shfl_xor_sync(~0u, ss, off);
    }
    __shared__ float red[16];
    __shared__ float mean_s, rstd_s;
    int w8 = threadIdx.x >> 5;
    if ((threadIdx.x & 31) == 0) { red[w8] = s; red[8 + w8] = ss; }
    __syncthreads();
    if (threadIdx.x == 0) {
        float S = 0.f, SS = 0.f;
#pragma unroll
        for (int i = 0; i < 8; i++) { S += red[i]; SS += red[8 + i]; }
        float m = S * (1.0f / Cc);
        float var = SS * (1.0f / Cc) - m * m;
        mean_s = m; rstd_s = rsqrtf(var + LN_EPS);
    }
    __syncthreads();
    float m = mean_s, r = rstd_s;
    float* orow = o + (size_t)row * Cc;
#pragma unroll
    for (int i = 0; i < 4; i++) {
        int c = threadIdx.x + i * 256;
        orow[c] = (v[i] - m) * r * w[c] + b[c];
    }
}

// ---------------- bucketed local attention: one block per (bucket, head, batch) ----------------
constexpr int ATTN_SMEM = (64 * 65 + 128 * 65 + 128 * 65 + 64 * 129) * 4;  // 116224 B

__global__ __launch_bounds__(256)
void attn_kernel(const float* __restrict__ qkv, float* __restrict__ ctx)
{
    extern __shared__ float sm[];
    float* q  = sm;                  // [64][65]
    float* kc = q + 64 * 65;         // [128][65]  (rows 0..63 = prev bucket, 64..127 = current)
    float* vc = kc + 128 * 65;       // [128][65]
    float* s  = vc + 128 * 65;       // [64][129]

    const int n = blockIdx.x, h = blockIdx.y, bb = blockIdx.z;
    const int tid = threadIdx.x;
    const size_t rowbase = (size_t)(bb * Tt + n * BSz);
    const float* base = qkv + rowbase * (3 * Cc);
    const int hoff = h * HD;

    for (int e = tid; e < 64 * 64; e += 256) {
        int i = e >> 6, d = e & 63;
        q[i * 65 + d] = base[(size_t)i * 3072 + hoff + d];
    }
    for (int e = tid; e < 128 * 64; e += 256) {
        int j = e >> 6, d = e & 63;
        float kv, vv;
        if (j < 64) {
            if (n == 0) { kv = 0.f; vv = 0.f; }           // bucket 0's "previous" is zeros
            else {
                const float* pb = qkv + (rowbase - 64 + j) * 3072;
                kv = pb[1024 + hoff + d]; vv = pb[2048 + hoff + d];
            }
        } else {
            const float* cb = base + (size_t)(j - 64) * 3072;
            kv = cb[1024 + hoff + d]; vv = cb[2048 + hoff + d];
        }
        kc[j * 65 + d] = kv; vc[j * 65 + d] = vv;
    }
    __syncthreads();

    // scores: thread (i = tid/4, jq = tid%4) computes 32 of the 128 keys for query i
    {
        int i = tid >> 2, jq = tid & 3;
        float acc[32];
#pragma unroll
        for (int jj = 0; jj < 32; jj++) acc[jj] = 0.f;
#pragma unroll 4
        for (int d = 0; d < 64; d++) {
            float qv = q[i * 65 + d];
#pragma unroll
            for (int jj = 0; jj < 32; jj++)
                acc[jj] += qv * kc[(jq + jj * 4) * 65 + d];
        }
#pragma unroll
        for (int jj = 0; jj < 32; jj++) {
            int j = jq + jj * 4;
            bool vis = (j < 64) || ((j - 64) <= i);
            s[i * 129 + j] = vis ? acc[jj] * ATT_SCALE : -1e30f;
        }
    }
    __syncthreads();

    // softmax per query row (threads 0..63)
    if (tid < 64) {
        float mx = -1e30f;
        for (int j = 0; j < 128; j++) mx = fmaxf(mx, s[tid * 129 + j]);
        float sum = 0.f;
        for (int j = 0; j < 128; j++) {
            float e = expf(s[tid * 129 + j] - mx);
            s[tid * 129 + j] = e; sum += e;
        }
        float inv = 1.0f / sum;
        for (int j = 0; j < 128; j++) s[tid * 129 + j] *= inv;
    }
    __syncthreads();

    // output: thread (i = tid/4, dq = tid%4) computes 16 of the 64 head dims for query i
    {
        int i = tid >> 2, dq = tid & 3;
        float acc[16];
#pragma unroll
        for (int dd = 0; dd < 16; dd++) acc[dd] = 0.f;
        for (int j = 0; j < 128; j++) {
            float av = s[i * 129 + j];
#pragma unroll
            for (int dd = 0; dd < 16; dd++)
                acc[dd] += av * vc[j * 65 + dq + dd * 4];
        }
        float* orow = ctx + (rowbase + i) * Cc + hoff;
#pragma unroll
        for (int dd = 0; dd < 16; dd++) orow[dq + dd * 4] = acc[dd];
    }
}

// ---------------- critic head (warp-per-row dot) + logstd copy ----------------
__global__ __launch_bounds__(256)
void head_small_kernel(const float* __restrict__ hbuf, const float* __restrict__ cw,
                       const float* __restrict__ cb, const float* __restrict__ lstd,
                       float* __restrict__ out)
{
    int row = blockIdx.x * 8 + (threadIdx.x >> 5);
    int lane = threadIdx.x & 31;
    const float* hr = hbuf + (size_t)row * Cc;
    float sum = 0.f;
#pragma unroll 8
    for (int k = lane; k < Cc; k += 32) sum += hr[k] * cw[k];
#pragma unroll
    for (int off = 16; off; off >>= 1) sum += __shfl_xor_sync(~0u, sum, off);
    if (lane == 0) out[(size_t)Mm * Aa + Aa + row] = sum + cb[0];
    if (blockIdx.x == 0 && threadIdx.x < Aa) out[(size_t)Mm * Aa + threadIdx.x] = lstd[threadIdx.x];
}

// ---------------- launcher ----------------
extern "C" void kernel_launch(void* const* d_in, const int* in_sizes, int n_in,
                              void* d_out, int out_size)
{
    const float* states = (const float*)d_in[0];
    const float* se_w   = (const float*)d_in[1];
    const float* se_b   = (const float*)d_in[2];
    const float* pos    = (const float*)d_in[3];
    const float* ln1w   = (const float*)d_in[4];
    const float* ln1b   = (const float*)d_in[5];
    const float* qkvw   = (const float*)d_in[6];
    const float* qkvb   = (const float*)d_in[7];
    const float* aow    = (const float*)d_in[8];
    const float* aob    = (const float*)d_in[9];
    const float* ln2w   = (const float*)d_in[10];
    const float* ln2b   = (const float*)d_in[11];
    const float* w1     = (const float*)d_in[12];
    const float* b1     = (const float*)d_in[13];
    const float* w2     = (const float*)d_in[14];
    const float* b2     = (const float*)d_in[15];
    const float* lnfw   = (const float*)d_in[16];
    const float* lnfb   = (const float*)d_in[17];
    const float* actw   = (const float*)d_in[18];
    const float* actb   = (const float*)d_in[19];
    const float* lstd   = (const float*)d_in[20];
    const float* crw    = (const float*)d_in[21];
    const float* crb    = (const float*)d_in[22];
    float* out = (float*)d_out;

    float *x, *hbuf, *qkv, *ctxb, *mlp;
    cudaGetSymbolAddress((void**)&x,    g_x);
    cudaGetSymbolAddress((void**)&hbuf, g_h);
    cudaGetSymbolAddress((void**)&qkv,  g_qkv);
    cudaGetSymbolAddress((void**)&ctxb, g_ctx);
    cudaGetSymbolAddress((void**)&mlp,  g_mlp);

    cudaFuncSetAttribute(attn_kernel, cudaFuncAttributeMaxDynamicSharedMemorySize, ATTN_SMEM);

    dim3 blk(256);
    const dim3 gridC (Cc     / BN, Mm / BM);   // N=1024
    const dim3 grid3C(3 * Cc / BN, Mm / BM);   // N=3072
    const dim3 grid4C(4 * Cc / BN, Mm / BM);   // N=4096

    // x = states @ se_w + se_b + pos
    gemm_tf32_kernel<3><<<gridC, blk>>>(states, se_w, se_b, pos, x, Mm, Cc, SD);

    for (int l = 0; l < Ll; l++) {
        ln_kernel<<<Mm, 256>>>(x, ln1w + l * Cc, ln1b + l * Cc, hbuf);
        gemm_tf32_kernel<0><<<grid3C, blk>>>(hbuf, qkvw + (size_t)l * Cc * 3 * Cc,
                                             qkvb + (size_t)l * 3 * Cc, nullptr,
                                             qkv, Mm, 3 * Cc, Cc);
        attn_kernel<<<dim3(Tt / BSz, Hh, Bb), 256, ATTN_SMEM>>>(qkv, ctxb);
        gemm_tf32_kernel<2><<<gridC, blk>>>(ctxb, aow + (size_t)l * Cc * Cc,
                                            aob + (size_t)l * Cc, x, x, Mm, Cc, Cc);
        ln_kernel<<<Mm, 256>>>(x, ln2w + l * Cc, ln2b + l * Cc, hbuf);
        gemm_tf32_kernel<1><<<grid4C, blk>>>(hbuf, w1 + (size_t)l * Cc * 4 * Cc,
                                             b1 + (size_t)l * 4 * Cc, nullptr,
                                             mlp, Mm, 4 * Cc, Cc);
        gemm_tf32_kernel<2><<<gridC, blk>>>(mlp, w2 + (size_t)l * 4 * Cc * Cc,
                                            b2 + (size_t)l * Cc, x, x, Mm, Cc, 4 * Cc);
    }

    ln_kernel<<<Mm, 256>>>(x, lnfw, lnfb, hbuf);
    // logits -> out[0 : M*A]   (row-major [B*T, A] matches flattened [B,T,A])
    gemm_tf32_kernel<0><<<dim3(1, Mm / BM), blk>>>(hbuf, actw, actb, nullptr, out, Mm, Aa, Cc);
    // logstd -> out[M*A : M*A+A], values -> out[M*A+A : end]
    head_small_kernel<<<Mm / 8, 256>>>(hbuf, crw, crb, lstd, out);
}

// round 3
// speedup vs baseline: 1.0054x; 1.0054x over previous
#include <cuda_runtime.h>
#include <mma.h>
#include <cstdint>
#include <cmath>

using namespace nvcuda;

// ---------------- problem dims ----------------
constexpr int Bb = 4, Tt = 4096, SD = 256, Cc = 1024, Aa = 64, Ll = 6, Hh = 16, BSz = 64;
constexpr int Mm = Bb * Tt;          // 16384 rows
constexpr int HD = Cc / Hh;          // 64
constexpr float ATT_SCALE = 0.125f;  // 1/sqrt(64)
constexpr float LN_EPS = 1e-5f;

// ---------------- scratch (device globals; no allocation allowed) ----------------
__device__ float g_x[(size_t)Mm * Cc];            // residual stream
__device__ float g_h[(size_t)Mm * Cc];            // LN output
__device__ float g_qkv[(size_t)Mm * 3 * Cc];      // qkv
__device__ float g_ctx[(size_t)Mm * Cc];          // attention context
__device__ float g_mlp[(size_t)Mm * 4 * Cc];      // mlp hidden

// ---------------- tf32 GEMM: out = EPI(A[M,K] @ W[K,N] + bias) ----------------
// EPI: 0 = +bias; 1 = gelu(+bias); 2 = +bias + aux[row*N+col] (residual);
//      3 = +bias + aux[(row % T)*N + col] (positional embed)
constexpr int BM = 128, BN = 128, BK = 32;

__device__ __forceinline__ float gelu_exact(float x) {
    return 0.5f * x * (1.0f + erff(x * 0.70710678118654752f));
}

template <int EPI>
__global__ __launch_bounds__(256)
void gemm_tf32_kernel(const float* __restrict__ A, const float* __restrict__ Bw,
                      const float* __restrict__ bias, const float* __restrict__ aux,
                      float* __restrict__ out, int M, int N, int K)
{
    __shared__ float As[BM][BK + 4];     // 18.4 KB
    __shared__ float Bs[BK][BN + 4];     // 16.9 KB
    __shared__ float stage[8][16][20];   // 10.2 KB epilogue staging (ldm=20, mult of 4)

    const int tid = threadIdx.x;
    const int w = tid >> 5, lane = tid & 31;
    const int warpM = w >> 2, warpN = w & 3;           // 2 x 4 warps
    const int m0 = blockIdx.y * BM, n0 = blockIdx.x * BN;

    wmma::fragment<wmma::accumulator, 16, 16, 8, float> acc[4][2];
#pragma unroll
    for (int i = 0; i < 4; i++)
#pragma unroll
        for (int j = 0; j < 2; j++) wmma::fill_fragment(acc[i][j], 0.0f);

    int aRow[4], aC4[4], bRow[4], bC4[4];
#pragma unroll
    for (int i = 0; i < 4; i++) {
        int lin = tid + i * 256;
        aRow[i] = lin >> 3;  aC4[i] = lin & 7;    // 128 rows x 8 float4
        bRow[i] = lin >> 5;  bC4[i] = lin & 31;   // 32 rows x 32 float4
    }

    const int nk = K / BK;
    float4 ra[4], rb[4];

#pragma unroll
    for (int i = 0; i < 4; i++) {
        ra[i] = *(const float4*)(A + (size_t)(m0 + aRow[i]) * K + aC4[i] * 4);
        int col = n0 + bC4[i] * 4;
        rb[i] = (col < N) ? *(const float4*)(Bw + (size_t)bRow[i] * N + col)
                          : make_float4(0.f, 0.f, 0.f, 0.f);
    }

    for (int kt = 0; kt < nk; kt++) {
        // store current tile to smem with round-to-nearest tf32 conversion
#pragma unroll
        for (int i = 0; i < 4; i++) {
            float* pa = &As[aRow[i]][aC4[i] * 4];
            pa[0] = wmma::__float_to_tf32(ra[i].x);
            pa[1] = wmma::__float_to_tf32(ra[i].y);
            pa[2] = wmma::__float_to_tf32(ra[i].z);
            pa[3] = wmma::__float_to_tf32(ra[i].w);
            float* pb = &Bs[bRow[i]][bC4[i] * 4];
            pb[0] = wmma::__float_to_tf32(rb[i].x);
            pb[1] = wmma::__float_to_tf32(rb[i].y);
            pb[2] = wmma::__float_to_tf32(rb[i].z);
            pb[3] = wmma::__float_to_tf32(rb[i].w);
        }
        __syncthreads();

        if (kt + 1 < nk) {  // prefetch next tile into registers
            int kbase = (kt + 1) * BK;
#pragma unroll
            for (int i = 0; i < 4; i++) {
                ra[i] = *(const float4*)(A + (size_t)(m0 + aRow[i]) * K + kbase + aC4[i] * 4);
                int col = n0 + bC4[i] * 4;
                rb[i] = (col < N) ? *(const float4*)(Bw + (size_t)(kbase + bRow[i]) * N + col)
                                  : make_float4(0.f, 0.f, 0.f, 0.f);
            }
        }

#pragma unroll
        for (int kk = 0; kk < BK; kk += 8) {
            wmma::fragment<wmma::matrix_b, 16, 16, 8, wmma::precision::tf32, wmma::row_major> bf[2];
#pragma unroll
            for (int in = 0; in < 2; in++)
                wmma::load_matrix_sync(bf[in], &Bs[kk][warpN * 32 + in * 16], BN + 4);
#pragma unroll
            for (int im = 0; im < 4; im++) {
                wmma::fragment<wmma::matrix_a, 16, 16, 8, wmma::precision::tf32, wmma::row_major> af;
                wmma::load_matrix_sync(af, &As[warpM * 64 + im * 16][kk], BK + 4);
#pragma unroll
                for (int in = 0; in < 2; in++)
                    wmma::mma_sync(acc[im][in], af, bf[in], acc[im][in]);
            }
        }
        __syncthreads();
    }

    // epilogue: stage each 16x16 fragment through smem, apply bias/activation
#pragma unroll
    for (int im = 0; im < 4; im++) {
#pragma unroll
        for (int in = 0; in < 2; in++) {
            wmma::store_matrix_sync(&stage[w][0][0], acc[im][in], 20, wmma::mem_row_major);
            __syncwarp();
            int rbase = m0 + warpM * 64 + im * 16;
            int cbase = n0 + warpN * 32 + in * 16;
#pragma unroll
            for (int e = 0; e < 8; e++) {
                int idx = lane + e * 32;
                int r = idx >> 4, c = idx & 15;
                int col = cbase + c;
                if (col < N) {
                    size_t o = (size_t)(rbase + r) * N + col;
                    float v = stage[w][r][c] + bias[col];
                    if (EPI == 1) v = gelu_exact(v);
                    else if (EPI == 2) v += aux[o];
                    else if (EPI == 3) v += aux[(size_t)((rbase + r) & (Tt - 1)) * N + col];
                    out[o] = v;
                }
            }
            __syncwarp();
        }
    }
}

// ---------------- LayerNorm: one block per row of C=1024 ----------------
__global__ __launch_bounds__(256)
void ln_kernel(const float* __restrict__ x, const float* __restrict__ w,
               const float* __restrict__ b, float* __restrict__ o)
{
    int row = blockIdx.x;
    const float* xr = x + (size_t)row * Cc;
    float v[4];
    float s = 0.f, ss = 0.f;
#pragma unroll
    for (int i = 0; i < 4; i++) {
        v[i] = xr[threadIdx.x + i * 256];
        s += v[i]; ss += v[i] * v[i];
    }
#pragma unroll
    for (int off = 16; off; off >>= 1) {
        s  += __shfl_xor_sync(~0u, s, off);
        ss += __shfl_xor_sync(~0u, ss, off);
    }
    __shared__ float red[16];
    __shared__ float mean_s, rstd_s;
    int w8 = threadIdx.x >> 5;
    if ((threadIdx.x & 31) == 0) { red[w8] = s; red[8 + w8] = ss; }
    __syncthreads();
    if (threadIdx.x == 0) {
        float S = 0.f, SS = 0.f;
#pragma unroll
        for (int i = 0; i < 8; i++) { S += red[i]; SS += red[8 + i]; }
        float m = S * (1.0f / Cc);
        float var = SS * (1.0f / Cc) - m * m;
        mean_s = m; rstd_s = rsqrtf(var + LN_EPS);
    }
    __syncthreads();
    float m = mean_s, r = rstd_s;
    float* orow = o + (size_t)row * Cc;
#pragma unroll
    for (int i = 0; i < 4; i++) {
        int c = threadIdx.x + i * 256;
        orow[c] = (v[i] - m) * r * w[c] + b[c];
    }
}

// ---------------- bucketed local attention: one block per (bucket, head, batch) ----------------
constexpr int ATTN_SMEM = (64 * 65 + 128 * 65 + 128 * 65 + 64 * 129) * 4;  // 116224 B

__global__ __launch_bounds__(256)
void attn_kernel(const float* __restrict__ qkv, float* __restrict__ ctx)
{
    extern __shared__ float sm[];
    float* q  = sm;                  // [64][65]
    float* kc = q + 64 * 65;         // [128][65]  (rows 0..63 = prev bucket, 64..127 = current)
    float* vc = kc + 128 * 65;       // [128][65]
    float* s  = vc + 128 * 65;       // [64][129]

    const int n = blockIdx.x, h = blockIdx.y, bb = blockIdx.z;
    const int tid = threadIdx.x;
    const size_t rowbase = (size_t)(bb * Tt + n * BSz);
    const float* base = qkv + rowbase * (3 * Cc);
    const int hoff = h * HD;

    for (int e = tid; e < 64 * 64; e += 256) {
        int i = e >> 6, d = e & 63;
        q[i * 65 + d] = base[(size_t)i * 3072 + hoff + d];
    }
    for (int e = tid; e < 128 * 64; e += 256) {
        int j = e >> 6, d = e & 63;
        float kv, vv;
        if (j < 64) {
            if (n == 0) { kv = 0.f; vv = 0.f; }           // bucket 0's "previous" is zeros
            else {
                const float* pb = qkv + (rowbase - 64 + j) * 3072;
                kv = pb[1024 + hoff + d]; vv = pb[2048 + hoff + d];
            }
        } else {
            const float* cb = base + (size_t)(j - 64) * 3072;
            kv = cb[1024 + hoff + d]; vv = cb[2048 + hoff + d];
        }
        kc[j * 65 + d] = kv; vc[j * 65 + d] = vv;
    }
    __syncthreads();

    // scores: thread (i = tid/4, jq = tid%4) computes 32 of the 128 keys for query i
    {
        int i = tid >> 2, jq = tid & 3;
        float acc[32];
#pragma unroll
        for (int jj = 0; jj < 32; jj++) acc[jj] = 0.f;
#pragma unroll 4
        for (int d = 0; d < 64; d++) {
            float qv = q[i * 65 + d];
#pragma unroll
            for (int jj = 0; jj < 32; jj++)
                acc[jj] += qv * kc[(jq + jj * 4) * 65 + d];
        }
#pragma unroll
        for (int jj = 0; jj < 32; jj++) {
            int j = jq + jj * 4;
            bool vis = (j < 64) || ((j - 64) <= i);
            s[i * 129 + j] = vis ? acc[jj] * ATT_SCALE : -1e30f;
        }
    }
    __syncthreads();

    // softmax per query row (threads 0..63)
    if (tid < 64) {
        float mx = -1e30f;
        for (int j = 0; j < 128; j++) mx = fmaxf(mx, s[tid * 129 + j]);
        float sum = 0.f;
        for (int j = 0; j < 128; j++) {
            float e = expf(s[tid * 129 + j] - mx);
            s[tid * 129 + j] = e; sum += e;
        }
        float inv = 1.0f / sum;
        for (int j = 0; j < 128; j++) s[tid * 129 + j] *= inv;
    }
    __syncthreads();

    // output: thread (i = tid/4, dq = tid%4) computes 16 of the 64 head dims for query i
    {
        int i = tid >> 2, dq = tid & 3;
        float acc[16];
#pragma unroll
        for (int dd = 0; dd < 16; dd++) acc[dd] = 0.f;
        for (int j = 0; j < 128; j++) {
            float av = s[i * 129 + j];
#pragma unroll
            for (int dd = 0; dd < 16; dd++)
                acc[dd] += av * vc[j * 65 + dq + dd * 4];
        }
        float* orow = ctx + (rowbase + i) * Cc + hoff;
#pragma unroll
        for (int dd = 0; dd < 16; dd++) orow[dq + dd * 4] = acc[dd];
    }
}

// ---------------- critic head (warp-per-row dot) + logstd copy ----------------
__global__ __launch_bounds__(256)
void head_small_kernel(const float* __restrict__ hbuf, const float* __restrict__ cw,
                       const float* __restrict__ cb, const float* __restrict__ lstd,
                       float* __restrict__ out)
{
    int row = blockIdx.x * 8 + (threadIdx.x >> 5);
    int lane = threadIdx.x & 31;
    const float* hr = hbuf + (size_t)row * Cc;
    float sum = 0.f;
#pragma unroll 8
    for (int k = lane; k < Cc; k += 32) sum += hr[k] * cw[k];
#pragma unroll
    for (int off = 16; off; off >>= 1) sum += __shfl_xor_sync(~0u, sum, off);
    if (lane == 0) out[(size_t)Mm * Aa + Aa + row] = sum + cb[0];
    if (blockIdx.x == 0 && threadIdx.x < Aa) out[(size_t)Mm * Aa + threadIdx.x] = lstd[threadIdx.x];
}

// ---------------- launcher ----------------
extern "C" void kernel_launch(void* const* d_in, const int* in_sizes, int n_in,
                              void* d_out, int out_size)
{
    const float* states = (const float*)d_in[0];
    const float* se_w   = (const float*)d_in[1];
    const float* se_b   = (const float*)d_in[2];
    const float* pos    = (const float*)d_in[3];
    const float* ln1w   = (const float*)d_in[4];
    const float* ln1b   = (const float*)d_in[5];
    const float* qkvw   = (const float*)d_in[6];
    const float* qkvb   = (const float*)d_in[7];
    const float* aow    = (const float*)d_in[8];
    const float* aob    = (const float*)d_in[9];
    const float* ln2w   = (const float*)d_in[10];
    const float* ln2b   = (const float*)d_in[11];
    const float* w1     = (const float*)d_in[12];
    const float* b1     = (const float*)d_in[13];
    const float* w2     = (const float*)d_in[14];
    const float* b2     = (const float*)d_in[15];
    const float* lnfw   = (const float*)d_in[16];
    const float* lnfb   = (const float*)d_in[17];
    const float* actw   = (const float*)d_in[18];
    const float* actb   = (const float*)d_in[19];
    const float* lstd   = (const float*)d_in[20];
    const float* crw    = (const float*)d_in[21];
    const float* crb    = (const float*)d_in[22];
    float* out = (float*)d_out;

    float *x, *hbuf, *qkv, *ctxb, *mlp;
    cudaGetSymbolAddress((void**)&x,    g_x);
    cudaGetSymbolAddress((void**)&hbuf, g_h);
    cudaGetSymbolAddress((void**)&qkv,  g_qkv);
    cudaGetSymbolAddress((void**)&ctxb, g_ctx);
    cudaGetSymbolAddress((void**)&mlp,  g_mlp);

    cudaFuncSetAttribute(attn_kernel, cudaFuncAttributeMaxDynamicSharedMemorySize, ATTN_SMEM);

    dim3 blk(256);
    const dim3 gridC (Cc     / BN, Mm / BM);   // N=1024
    const dim3 grid3C(3 * Cc / BN, Mm / BM);   // N=3072
    const dim3 grid4C(4 * Cc / BN, Mm / BM);   // N=4096

    // x = states @ se_w + se_b + pos
    gemm_tf32_kernel<3><<<gridC, blk>>>(states, se_w, se_b, pos, x, Mm, Cc, SD);

    for (int l = 0; l < Ll; l++) {
        ln_kernel<<<Mm, 256>>>(x, ln1w + l * Cc, ln1b + l * Cc, hbuf);
        gemm_tf32_kernel<0><<<grid3C, blk>>>(hbuf, qkvw + (size_t)l * Cc * 3 * Cc,
                                             qkvb + (size_t)l * 3 * Cc, nullptr,
                                             qkv, Mm, 3 * Cc, Cc);
        attn_kernel<<<dim3(Tt / BSz, Hh, Bb), 256, ATTN_SMEM>>>(qkv, ctxb);
        gemm_tf32_kernel<2><<<gridC, blk>>>(ctxb, aow + (size_t)l * Cc * Cc,
                                            aob + (size_t)l * Cc, x, x, Mm, Cc, Cc);
        ln_kernel<<<Mm, 256>>>(x, ln2w + l * Cc, ln2b + l * Cc, hbuf);
        gemm_tf32_kernel<1><<<grid4C, blk>>>(hbuf, w1 + (size_t)l * Cc * 4 * Cc,
                                             b1 + (size_t)l * 4 * Cc, nullptr,
                                             mlp, Mm, 4 * Cc, Cc);
        gemm_tf32_kernel<2><<<gridC, blk>>>(mlp, w2 + (size_t)l * 4 * Cc * Cc,
                                            b2 + (size_t)l * Cc, x, x, Mm, Cc, 4 * Cc);
    }

    ln_kernel<<<Mm, 256>>>(x, lnfw, lnfb, hbuf);
    // logits -> out[0 : M*A]   (row-major [B*T, A] matches flattened [B,T,A])
    gemm_tf32_kernel<0><<<dim3(1, Mm / BM), blk>>>(hbuf, actw, actb, nullptr, out, Mm, Aa, Cc);
    // logstd -> out[M*A : M*A+A], values -> out[M*A+A : end]
    head_small_kernel<<<Mm / 8, 256>>>(hbuf, crw, crb, lstd, out);
}

// round 6
// speedup vs baseline: 1.1866x; 1.1802x over previous
#include <cuda_runtime.h>
#include <cuda_bf16.h>
#include <cstdint>
#include <cmath>

constexpr int Bb=4, Tt=4096, SD=256, Cc=1024, Aa=64, Ll=6, Hh=16, BSz=64;
constexpr int Mm=Bb*Tt, HD=Cc/Hh;
constexpr float ATT_SCALE=0.125f, LN_EPS=1e-5f;

// transposed bf16-plane weights, packed in one buffer (element offsets)
constexpr size_t SE_OFF=0;
constexpr size_t QKV_OFF=SE_OFF+1024UL*256, QKV_SZ=3072UL*1024;
constexpr size_t AO_OFF =QKV_OFF+6*QKV_SZ,  AO_SZ =1024UL*1024;
constexpr size_t W1_OFF =AO_OFF +6*AO_SZ,   W1_SZ =4096UL*1024;
constexpr size_t W2_OFF =W1_OFF +6*W1_SZ,   W2_SZ =1024UL*4096;
constexpr size_t ACT_OFF=W2_OFF +6*W2_SZ;
constexpr size_t WTOT   =ACT_OFF+64UL*1024;

__device__ float g_x  [(size_t)Mm*Cc];       // residual stream (fp32)
__device__ float g_qkv[(size_t)Mm*3*Cc];     // qkv (fp32, read by attention)
__device__ __nv_bfloat16 g_sh[(size_t)Mm*SD],   g_sl[(size_t)Mm*SD];     // states planes
__device__ __nv_bfloat16 g_hh[(size_t)Mm*Cc],   g_hl[(size_t)Mm*Cc];     // LN planes
__device__ __nv_bfloat16 g_ch[(size_t)Mm*Cc],   g_cl[(size_t)Mm*Cc];     // ctx planes
__device__ __nv_bfloat16 g_mh[(size_t)Mm*4*Cc], g_ml[(size_t)Mm*4*Cc];   // mlp planes
__device__ __nv_bfloat16 g_wh[WTOT], g_wl[WTOT];                          // weight planes

// ---------- helpers (base-target PTX only: cp.async / ldmatrix / mma.sync) ----------
__device__ __forceinline__ uint32_t smem_u32(const void* p){
    uint32_t a; asm("{ .reg .u64 t; cvta.to.shared.u64 t, %1; cvt.u32.u64 %0, t; }":"=r"(a):"l"(p)); return a;
}
__device__ __forceinline__ void cpa16(uint32_t dst, const void* src){
    asm volatile("cp.async.cg.shared.global [%0], [%1], 16;"::"r"(dst),"l"(src));
}
#define CP_COMMIT() asm volatile("cp.async.commit_group;":::"memory")
__device__ __forceinline__ void ldsm4(uint32_t* r, uint32_t a){
    asm volatile("ldmatrix.sync.aligned.m8n8.x4.shared.b16 {%0,%1,%2,%3}, [%4];"
        : "=r"(r[0]),"=r"(r[1]),"=r"(r[2]),"=r"(r[3]) : "r"(a));
}
__device__ __forceinline__ void mma16816(float* d, const uint32_t* a, const uint32_t* b){
    asm volatile("mma.sync.aligned.m16n8k16.row.col.f32.bf16.bf16.f32 "
        "{%0,%1,%2,%3}, {%4,%5,%6,%7}, {%8,%9}, {%0,%1,%2,%3};"
        : "+f"(d[0]),"+f"(d[1]),"+f"(d[2]),"+f"(d[3])
        : "r"(a[0]),"r"(a[1]),"r"(a[2]),"r"(a[3]), "r"(b[0]),"r"(b[1]));
}
__device__ __forceinline__ float gelu_exact(float x){
    return 0.5f*x*(1.0f+erff(x*0.70710678118654752f));
}
__device__ __forceinline__ void split_store(float v, __nv_bfloat16* hi, __nv_bfloat16* lo, size_t o){
    __nv_bfloat16 h=__float2bfloat16_rn(v);
    hi[o]=h; lo[o]=__float2bfloat16_rn(v-__bfloat162float(h));
}

// ========== bf16 hi/lo 3-pass GEMM: out = EPI(A @ Bt^T + bias) ==========
// A planes [M][K], Bt planes [N][K] (K-major). CTA tile 128x128, K-step 16.
// smem row: 16 bf16 hi (32B) | 16 bf16 lo (32B), stride 80B (conflict-free ldmatrix).
// EPI: 0 = bias, fp32 out; 1 = gelu -> planes; 2 = +aux residual fp32; 3 = +pos-embed fp32
constexpr int STAGES=4, STAGE=20480, BOFF=10240;
constexpr int GSMEM=STAGES*STAGE;   // 81920 B

template<int EPI>
__global__ __launch_bounds__(256)
void gemmb(const __nv_bfloat16* __restrict__ Ahi, const __nv_bfloat16* __restrict__ Alo,
           const __nv_bfloat16* __restrict__ Bhi, const __nv_bfloat16* __restrict__ Blo,
           const float* __restrict__ bias, const float* __restrict__ aux,
           float* __restrict__ outF, __nv_bfloat16* __restrict__ oHi, __nv_bfloat16* __restrict__ oLo,
           int Nv, int K)
{
    extern __shared__ char smem[];
    const uint32_t sb = smem_u32(smem);
    const int tid=threadIdx.x, lane=tid&31, wid=tid>>5;
    const int wm=wid>>2, wn=wid&3;
    const int m0=blockIdx.y*128, n0=blockIdx.x*128;
    const int nk=K>>4;

    auto issue=[&](int st,int k0){
        uint32_t ab=sb+st*STAGE;
#pragma unroll
        for(int i=0;i<2;i++){
            int c=tid+i*256;
            int r=c>>2, q=c&3;
            const __nv_bfloat16* src=(q<2?Ahi:Alo)+(size_t)(m0+r)*K+k0+(q&1)*8;
            cpa16(ab+r*80+q*16, src);
        }
        uint32_t bbs=sb+st*STAGE+BOFF;
#pragma unroll
        for(int i=0;i<2;i++){
            int c=tid+i*256;
            int r=c>>2, q=c&3;
            int br=min(n0+r, Nv-1);
            const __nv_bfloat16* src=(q<2?Bhi:Blo)+(size_t)br*K+k0+(q&1)*8;
            cpa16(bbs+r*80+q*16, src);
        }
    };

    float acc[4][4][4];
#pragma unroll
    for(int a=0;a<4;a++)
#pragma unroll
    for(int b=0;b<4;b++)
#pragma unroll
    for(int c=0;c<4;c++) acc[a][b][c]=0.f;

    for(int s=0;s<STAGES-1;s++){ issue(s,s*16); CP_COMMIT(); }

    for(int s=0;s<nk;s++){
        asm volatile("cp.async.wait_group %0;"::"n"(STAGES-2));
        __syncthreads();
        uint32_t ab=sb+(s&3)*STAGE, bbs=ab+BOFF;

        uint32_t bfr[2][2][4];
#pragma unroll
        for(int g=0;g<2;g++)
#pragma unroll
        for(int p=0;p<2;p++){
            uint32_t nrow=wn*32+g*16+((lane>>4)&1)*8+(lane&7);
            uint32_t kby =((lane>>3)&1)*16+p*32;
            ldsm4(bfr[g][p], bbs+nrow*80+kby);
        }
        uint32_t afr[4][2][4];
#pragma unroll
        for(int mt=0;mt<4;mt++)
#pragma unroll
        for(int p=0;p<2;p++){
            uint32_t row=wm*64+mt*16+((lane>>3)&1)*8+(lane&7);
            uint32_t kby=((lane>>4)&1)*16+p*32;
            ldsm4(afr[mt][p], ab+row*80+kby);
        }
#pragma unroll
        for(int mt=0;mt<4;mt++)
#pragma unroll
        for(int nt=0;nt<4;nt++){
            const uint32_t* bh=&bfr[nt>>1][0][(nt&1)*2];
            const uint32_t* bl=&bfr[nt>>1][1][(nt&1)*2];
            mma16816(acc[mt][nt], afr[mt][0], bh);   // hi*hi
            mma16816(acc[mt][nt], afr[mt][0], bl);   // hi*lo
            mma16816(acc[mt][nt], afr[mt][1], bh);   // lo*hi
        }
        int ns=s+STAGES-1;
        if(ns<nk) issue(ns&3, ns*16);
        CP_COMMIT();
    }

    // ---- epilogue ----
    auto emit=[&](int r,int col,float v0,float v1){
        if(col<Nv){
            size_t o=(size_t)r*Nv+col;
            v0+=bias[col]; v1+=bias[col+1];
            if(EPI==1){
                v0=gelu_exact(v0); v1=gelu_exact(v1);
                __nv_bfloat16 h0=__float2bfloat16_rn(v0), h1=__float2bfloat16_rn(v1);
                __nv_bfloat162 hp; hp.x=h0; hp.y=h1;
                *(__nv_bfloat162*)(oHi+o)=hp;
                __nv_bfloat162 lp;
                lp.x=__float2bfloat16_rn(v0-__bfloat162float(h0));
                lp.y=__float2bfloat16_rn(v1-__bfloat162float(h1));
                *(__nv_bfloat162*)(oLo+o)=lp;
            } else if(EPI==2){
                float2 ax=*(const float2*)(aux+o);
                *(float2*)(outF+o)=make_float2(v0+ax.x, v1+ax.y);
            } else if(EPI==3){
                float2 ax=*(const float2*)(aux+(size_t)(r&(Tt-1))*Nv+col);
                *(float2*)(outF+o)=make_float2(v0+ax.x, v1+ax.y);
            } else {
                *(float2*)(outF+o)=make_float2(v0,v1);
            }
        }
    };
#pragma unroll
    for(int mt=0;mt<4;mt++)
#pragma unroll
    for(int nt=0;nt<4;nt++){
        int col=n0+wn*32+nt*8+2*(lane&3);
        int r0=m0+wm*64+mt*16+(lane>>2);
        emit(r0,   col, acc[mt][nt][0], acc[mt][nt][1]);
        emit(r0+8, col, acc[mt][nt][2], acc[mt][nt][3]);
    }
}

// ---------- weight transpose + split: W[K,N] -> planes[N][K] ----------
__global__ __launch_bounds__(256)
void trk(const float* __restrict__ W, __nv_bfloat16* __restrict__ hi,
         __nv_bfloat16* __restrict__ lo, int K, int N)
{
    __shared__ float t[32][33];
    int n0=blockIdx.x*32, k0=blockIdx.y*32;
    int tx=threadIdx.x&31, ty=threadIdx.x>>5;
#pragma unroll
    for(int i=0;i<4;i++) t[ty+i*8][tx]=W[(size_t)(k0+ty+i*8)*N+n0+tx];
    __syncthreads();
#pragma unroll
    for(int i=0;i<4;i++)
        split_store(t[tx][ty+i*8], hi, lo, (size_t)(n0+ty+i*8)*K+k0+tx);
}

__global__ __launch_bounds__(256)
void splitk(const float* __restrict__ x, __nv_bfloat16* __restrict__ hi, __nv_bfloat16* __restrict__ lo){
    size_t i=(size_t)blockIdx.x*256+threadIdx.x;
    split_store(x[i], hi, lo, i);
}

// ---------- LayerNorm -> planes ----------
__global__ __launch_bounds__(256)
void ln_kernel(const float* __restrict__ x, const float* __restrict__ w,
               const float* __restrict__ b, __nv_bfloat16* __restrict__ ohi,
               __nv_bfloat16* __restrict__ olo)
{
    int row=blockIdx.x;
    const float* xr=x+(size_t)row*Cc;
    float v[4], s=0.f, ss=0.f;
#pragma unroll
    for(int i=0;i<4;i++){ v[i]=xr[threadIdx.x+i*256]; s+=v[i]; ss+=v[i]*v[i]; }
#pragma unroll
    for(int off=16;off;off>>=1){ s+=__shfl_xor_sync(~0u,s,off); ss+=__shfl_xor_sync(~0u,ss,off); }
    __shared__ float red[16]; __shared__ float mean_s, rstd_s;
    int w8=threadIdx.x>>5;
    if((threadIdx.x&31)==0){ red[w8]=s; red[8+w8]=ss; }
    __syncthreads();
    if(threadIdx.x==0){
        float S=0.f,SS=0.f;
#pragma unroll
        for(int i=0;i<8;i++){ S+=red[i]; SS+=red[8+i]; }
        float m=S*(1.0f/Cc);
        mean_s=m; rstd_s=rsqrtf(SS*(1.0f/Cc)-m*m+LN_EPS);
    }
    __syncthreads();
    float m=mean_s, r=rstd_s;
    size_t rb=(size_t)row*Cc;
#pragma unroll
    for(int i=0;i<4;i++){
        int c=threadIdx.x+i*256;
        split_store((v[i]-m)*r*w[c]+b[c], ohi, olo, rb+c);
    }
}

// ---------- bucketed local attention -> ctx planes ----------
constexpr int ATTN_SMEM=(64*65+128*65+128*65+64*129)*4;

__global__ __launch_bounds__(256)
void attn_kernel(const float* __restrict__ qkv, __nv_bfloat16* __restrict__ chi,
                 __nv_bfloat16* __restrict__ clo)
{
    extern __shared__ float sm[];
    float* q=sm; float* kc=q+64*65; float* vc=kc+128*65; float* s=vc+128*65;
    const int n=blockIdx.x, h=blockIdx.y, bb=blockIdx.z;
    const int tid=threadIdx.x;
    const size_t rowbase=(size_t)(bb*Tt+n*BSz);
    const float* base=qkv+rowbase*(3*Cc);
    const int hoff=h*HD;

    for(int e=tid;e<64*64;e+=256){ int i=e>>6,d=e&63; q[i*65+d]=base[(size_t)i*3072+hoff+d]; }
    for(int e=tid;e<128*64;e+=256){
        int j=e>>6,d=e&63; float kv,vv;
        if(j<64){
            if(n==0){ kv=0.f; vv=0.f; }
            else{ const float* pb=qkv+(rowbase-64+j)*3072; kv=pb[1024+hoff+d]; vv=pb[2048+hoff+d]; }
        } else {
            const float* cb=base+(size_t)(j-64)*3072; kv=cb[1024+hoff+d]; vv=cb[2048+hoff+d];
        }
        kc[j*65+d]=kv; vc[j*65+d]=vv;
    }
    __syncthreads();
    {
        int i=tid>>2, jq=tid&3;
        float acc[32];
#pragma unroll
        for(int jj=0;jj<32;jj++) acc[jj]=0.f;
#pragma unroll 4
        for(int d=0;d<64;d++){
            float qv=q[i*65+d];
#pragma unroll
            for(int jj=0;jj<32;jj++) acc[jj]+=qv*kc[(jq+jj*4)*65+d];
        }
#pragma unroll
        for(int jj=0;jj<32;jj++){
            int j=jq+jj*4;
            bool vis=(j<64)||((j-64)<=i);
            s[i*129+j]=vis?acc[jj]*ATT_SCALE:-1e30f;
        }
    }
    __syncthreads();
    if(tid<64){
        float mx=-1e30f;
        for(int j=0;j<128;j++) mx=fmaxf(mx,s[tid*129+j]);
        float sum=0.f;
        for(int j=0;j<128;j++){ float e=expf(s[tid*129+j]-mx); s[tid*129+j]=e; sum+=e; }
        float inv=1.0f/sum;
        for(int j=0;j<128;j++) s[tid*129+j]*=inv;
    }
    __syncthreads();
    {
        int i=tid>>2, dq=tid&3;
        float acc[16];
#pragma unroll
        for(int dd=0;dd<16;dd++) acc[dd]=0.f;
        for(int j=0;j<128;j++){
            float av=s[i*129+j];
#pragma unroll
            for(int dd=0;dd<16;dd++) acc[dd]+=av*vc[j*65+dq+dd*4];
        }
        size_t ob=(rowbase+i)*Cc+hoff;
#pragma unroll
        for(int dd=0;dd<16;dd++) split_store(acc[dd], chi, clo, ob+dq+dd*4);
    }
}

// ---------- critic head + logstd (reads lnf planes) ----------
__global__ __launch_bounds__(256)
void head_small_kernel(const __nv_bfloat16* __restrict__ hh, const __nv_bfloat16* __restrict__ hl,
                       const float* __restrict__ cw, const float* __restrict__ cb,
                       const float* __restrict__ lstd, float* __restrict__ out)
{
    int row=blockIdx.x*8+(threadIdx.x>>5);
    int lane=threadIdx.x&31;
    size_t rb=(size_t)row*Cc;
    float sum=0.f;
#pragma unroll 8
    for(int k=lane;k<Cc;k+=32)
        sum+=(__bfloat162float(hh[rb+k])+__bfloat162float(hl[rb+k]))*cw[k];
#pragma unroll
    for(int off=16;off;off>>=1) sum+=__shfl_xor_sync(~0u,sum,off);
    if(lane==0) out[(size_t)Mm*Aa+Aa+row]=sum+cb[0];
    if(blockIdx.x==0 && threadIdx.x<Aa) out[(size_t)Mm*Aa+threadIdx.x]=lstd[threadIdx.x];
}

// ---------- launcher ----------
extern "C" void kernel_launch(void* const* d_in, const int* in_sizes, int n_in,
                              void* d_out, int out_size)
{
    const float* states=(const float*)d_in[0];
    const float* se_w=(const float*)d_in[1];  const float* se_b=(const float*)d_in[2];
    const float* pos =(const float*)d_in[3];
    const float* ln1w=(const float*)d_in[4];  const float* ln1b=(const float*)d_in[5];
    const float* qkvw=(const float*)d_in[6];  const float* qkvb=(const float*)d_in[7];
    const float* aow =(const float*)d_in[8];  const float* aob =(const float*)d_in[9];
    const float* ln2w=(const float*)d_in[10]; const float* ln2b=(const float*)d_in[11];
    const float* w1  =(const float*)d_in[12]; const float* b1  =(const float*)d_in[13];
    const float* w2  =(const float*)d_in[14]; const float* b2  =(const float*)d_in[15];
    const float* lnfw=(const float*)d_in[16]; const float* lnfb=(const float*)d_in[17];
    const float* actw=(const float*)d_in[18]; const float* actb=(const float*)d_in[19];
    const float* lstd=(const float*)d_in[20];
    const float* crw =(const float*)d_in[21]; const float* crb =(const float*)d_in[22];
    float* out=(float*)d_out;

    float *x,*qkv;
    __nv_bfloat16 *sh,*sl,*hh,*hl,*ch,*cl,*mh,*ml,*wh,*wl;
    cudaGetSymbolAddress((void**)&x,g_x);    cudaGetSymbolAddress((void**)&qkv,g_qkv);
    cudaGetSymbolAddress((void**)&sh,g_sh);  cudaGetSymbolAddress((void**)&sl,g_sl);
    cudaGetSymbolAddress((void**)&hh,g_hh);  cudaGetSymbolAddress((void**)&hl,g_hl);
    cudaGetSymbolAddress((void**)&ch,g_ch);  cudaGetSymbolAddress((void**)&cl,g_cl);
    cudaGetSymbolAddress((void**)&mh,g_mh);  cudaGetSymbolAddress((void**)&ml,g_ml);
    cudaGetSymbolAddress((void**)&wh,g_wh);  cudaGetSymbolAddress((void**)&wl,g_wl);

    cudaFuncSetAttribute(gemmb<0>, cudaFuncAttributeMaxDynamicSharedMemorySize, GSMEM);
    cudaFuncSetAttribute(gemmb<1>, cudaFuncAttributeMaxDynamicSharedMemorySize, GSMEM);
    cudaFuncSetAttribute(gemmb<2>, cudaFuncAttributeMaxDynamicSharedMemorySize, GSMEM);
    cudaFuncSetAttribute(gemmb<3>, cudaFuncAttributeMaxDynamicSharedMemorySize, GSMEM);
    cudaFuncSetAttribute(attn_kernel, cudaFuncAttributeMaxDynamicSharedMemorySize, ATTN_SMEM);

    // weight prep: transpose + hi/lo split
    trk<<<dim3(1024/32,256/32),256>>>(se_w, wh+SE_OFF, wl+SE_OFF, 256,1024);
    for(int l=0;l<Ll;l++){
        trk<<<dim3(3072/32,1024/32),256>>>(qkvw+(size_t)l*QKV_SZ, wh+QKV_OFF+l*QKV_SZ, wl+QKV_OFF+l*QKV_SZ, 1024,3072);
        trk<<<dim3(1024/32,1024/32),256>>>(aow +(size_t)l*AO_SZ,  wh+AO_OFF +l*AO_SZ,  wl+AO_OFF +l*AO_SZ,  1024,1024);
        trk<<<dim3(4096/32,1024/32),256>>>(w1  +(size_t)l*W1_SZ,  wh+W1_OFF +l*W1_SZ,  wl+W1_OFF +l*W1_SZ,  1024,4096);
        trk<<<dim3(1024/32,4096/32),256>>>(w2  +(size_t)l*W2_SZ,  wh+W2_OFF +l*W2_SZ,  wl+W2_OFF +l*W2_SZ,  4096,1024);
    }
    trk<<<dim3(64/32,1024/32),256>>>(actw, wh+ACT_OFF, wl+ACT_OFF, 1024,64);
    splitk<<<Mm*SD/256,256>>>(states, sh, sl);

    const dim3 gC(8,Mm/128), g3C(24,Mm/128), g4C(32,Mm/128), gA(1,Mm/128);

    // x = states @ se_w + se_b + pos
    gemmb<3><<<gC,256,GSMEM>>>(sh,sl, wh+SE_OFF,wl+SE_OFF, se_b, pos, x,nullptr,nullptr, 1024,256);

    for(int l=0;l<Ll;l++){
        ln_kernel<<<Mm,256>>>(x, ln1w+l*Cc, ln1b+l*Cc, hh, hl);
        gemmb<0><<<g3C,256,GSMEM>>>(hh,hl, wh+QKV_OFF+l*QKV_SZ,wl+QKV_OFF+l*QKV_SZ,
                                    qkvb+(size_t)l*3072, nullptr, qkv,nullptr,nullptr, 3072,1024);
        attn_kernel<<<dim3(Tt/BSz,Hh,Bb),256,ATTN_SMEM>>>(qkv, ch, cl);
        gemmb<2><<<gC,256,GSMEM>>>(ch,cl, wh+AO_OFF+l*AO_SZ,wl+AO_OFF+l*AO_SZ,
                                   aob+(size_t)l*1024, x, x,nullptr,nullptr, 1024,1024);
        ln_kernel<<<Mm,256>>>(x, ln2w+l*Cc, ln2b+l*Cc, hh, hl);
        gemmb<1><<<g4C,256,GSMEM>>>(hh,hl, wh+W1_OFF+l*W1_SZ,wl+W1_OFF+l*W1_SZ,
                                    b1+(size_t)l*4096, nullptr, nullptr,mh,ml, 4096,1024);
        gemmb<2><<<gC,256,GSMEM>>>(mh,ml, wh+W2_OFF+l*W2_SZ,wl+W2_OFF+l*W2_SZ,
                                   b2+(size_t)l*1024, x, x,nullptr,nullptr, 1024,4096);
    }

    ln_kernel<<<Mm,256>>>(x, lnfw, lnfb, hh, hl);
    gemmb<0><<<gA,256,GSMEM>>>(hh,hl, wh+ACT_OFF,wl+ACT_OFF, actb, nullptr, out,nullptr,nullptr, 64,1024);
    head_small_kernel<<<Mm/8,256>>>(hh, hl, crw, crb, lstd, out);
}

// round 8
// speedup vs baseline: 3.0884x; 2.6027x over previous
#include <cuda_runtime.h>
#include <cuda_fp16.h>
#include <cstdint>
#include <cmath>

constexpr int Bb=4, Tt=4096, SD=256, Cc=1024, Aa=64, Ll=6, Hh=16, BSz=64;
constexpr int Mm=Bb*Tt, HD=Cc/Hh;
constexpr float ATT_SCALE=0.125f, LN_EPS=1e-5f;

// transposed fp16 weights, packed (element offsets)
constexpr size_t SE_OFF=0;
constexpr size_t QKV_OFF=SE_OFF+1024UL*256, QKV_SZ=3072UL*1024;
constexpr size_t AO_OFF =QKV_OFF+6*QKV_SZ,  AO_SZ =1024UL*1024;
constexpr size_t W1_OFF =AO_OFF +6*AO_SZ,   W1_SZ =4096UL*1024;
constexpr size_t W2_OFF =W1_OFF +6*W1_SZ,   W2_SZ =1024UL*4096;
constexpr size_t WTOT   =W2_OFF +6*W2_SZ;

__device__ float g_x  [(size_t)Mm*Cc];       // residual stream (fp32)
__device__ float g_qkv[(size_t)Mm*3*Cc];     // qkv fp32 / final-LN fp32 reuse
__device__ __half g_sh[(size_t)Mm*SD];       // states fp16
__device__ __half g_hh[(size_t)Mm*Cc];       // LN out fp16
__device__ __half g_ch[(size_t)Mm*Cc];       // attn ctx fp16
__device__ __half g_mh[(size_t)Mm*4*Cc];     // mlp hidden fp16
__device__ __half g_wh[WTOT];                // weights fp16 [N][K]

// ---------- base-target PTX helpers ----------
__device__ __forceinline__ uint32_t smem_u32(const void* p){
    uint32_t a; asm("{ .reg .u64 t; cvta.to.shared.u64 t, %1; cvt.u32.u64 %0, t; }":"=r"(a):"l"(p)); return a;
}
__device__ __forceinline__ void cpa16(uint32_t dst, const void* src){
    asm volatile("cp.async.cg.shared.global [%0], [%1], 16;"::"r"(dst),"l"(src));
}
#define CP_COMMIT() asm volatile("cp.async.commit_group;":::"memory")
__device__ __forceinline__ void ldsm4(uint32_t* r, uint32_t a){
    asm volatile("ldmatrix.sync.aligned.m8n8.x4.shared.b16 {%0,%1,%2,%3}, [%4];"
        : "=r"(r[0]),"=r"(r[1]),"=r"(r[2]),"=r"(r[3]) : "r"(a));
}
__device__ __forceinline__ void mma16816(float* d, const uint32_t* a, const uint32_t* b){
    asm volatile("mma.sync.aligned.m16n8k16.row.col.f32.f16.f16.f32 "
        "{%0,%1,%2,%3}, {%4,%5,%6,%7}, {%8,%9}, {%0,%1,%2,%3};"
        : "+f"(d[0]),"+f"(d[1]),"+f"(d[2]),"+f"(d[3])
        : "r"(a[0]),"r"(a[1]),"r"(a[2]),"r"(a[3]), "r"(b[0]),"r"(b[1]));
}
__device__ __forceinline__ float gelu_exact(float x){
    return 0.5f*x*(1.0f+erff(x*0.70710678118654752f));
}

// ========== fp16 single-pass GEMM: out = EPI(A[M,K] @ Bt[N,K]^T + bias) ==========
// CTA tile 128x128, K-step 32, 4-stage cp.async pipeline.
// smem row: 32 fp16 (64B data) in 80B stride (conflict-free ldmatrix).
// EPI: 0 = fp32 out; 1 = gelu -> fp16; 2 = +aux residual fp32; 3 = +pos-embed fp32
constexpr int STAGE=20480, BOFF=10240, GSMEM=4*STAGE;  // 81920 B

template<int EPI>
__global__ __launch_bounds__(256)
void gemmh(const __half* __restrict__ Ah, const __half* __restrict__ Bt,
           const float* __restrict__ bias, const float* __restrict__ aux,
           float* __restrict__ outF, __half* __restrict__ oH, int Nv, int K)
{
    extern __shared__ char smem[];
    const uint32_t sb = smem_u32(smem);
    const int tid=threadIdx.x, lane=tid&31, wid=tid>>5;
    const int wm=wid>>2, wn=wid&3;
    const int m0=blockIdx.y*128, n0=blockIdx.x*128;
    const int nk=K>>5;

    auto issue=[&](int st,int k0){
        uint32_t ab=sb+(st&3)*STAGE;
#pragma unroll
        for(int i=0;i<2;i++){
            int c=tid+i*256;
            int r=c>>2, q=c&3;
            cpa16(ab+r*80+q*16,       Ah+(size_t)(m0+r)*K+k0+q*8);
            cpa16(ab+BOFF+r*80+q*16,  Bt+(size_t)(n0+r)*K+k0+q*8);
        }
    };

    float acc[4][4][4];
#pragma unroll
    for(int a=0;a<4;a++)
#pragma unroll
    for(int b=0;b<4;b++)
#pragma unroll
    for(int c=0;c<4;c++) acc[a][b][c]=0.f;

    for(int s=0;s<3 && s<nk;s++){ issue(s,s*32); CP_COMMIT(); }

    for(int s=0;s<nk;s++){
        asm volatile("cp.async.wait_group 2;":::"memory");
        __syncthreads();
        uint32_t ab=sb+(s&3)*STAGE, bbs=ab+BOFF;
#pragma unroll
        for(int p=0;p<2;p++){
            uint32_t bfr[2][4];
#pragma unroll
            for(int g=0;g<2;g++){
                uint32_t nrow=wn*32+g*16+((lane>>4)&1)*8+(lane&7);
                uint32_t kby =((lane>>3)&1)*16+p*32;
                ldsm4(bfr[g], bbs+nrow*80+kby);
            }
            uint32_t afr[4][4];
#pragma unroll
            for(int mt=0;mt<4;mt++){
                uint32_t row=wm*64+mt*16+((lane>>3)&1)*8+(lane&7);
                uint32_t kby=((lane>>4)&1)*16+p*32;
                ldsm4(afr[mt], ab+row*80+kby);
            }
#pragma unroll
            for(int mt=0;mt<4;mt++)
#pragma unroll
            for(int nt=0;nt<4;nt++)
                mma16816(acc[mt][nt], afr[mt], &bfr[nt>>1][(nt&1)*2]);
        }
        if(s+3<nk) issue(s+3,(s+3)*32);
        CP_COMMIT();
    }

    // ---- epilogue ----
#pragma unroll
    for(int mt=0;mt<4;mt++)
#pragma unroll
    for(int nt=0;nt<4;nt++){
        int col=n0+wn*32+nt*8+2*(lane&3);
        int r0=m0+wm*64+mt*16+(lane>>2);
        float2 bv=*(const float2*)(bias+col);
#pragma unroll
        for(int hrow=0;hrow<2;hrow++){
            int r=r0+hrow*8;
            float v0=acc[mt][nt][hrow*2+0]+bv.x;
            float v1=acc[mt][nt][hrow*2+1]+bv.y;
            size_t o=(size_t)r*Nv+col;
            if(EPI==1){
                v0=gelu_exact(v0); v1=gelu_exact(v1);
                __half2 hp; hp.x=__float2half_rn(v0); hp.y=__float2half_rn(v1);
                *(__half2*)(oH+o)=hp;
            } else if(EPI==2){
                float2 ax=*(const float2*)(aux+o);
                *(float2*)(outF+o)=make_float2(v0+ax.x, v1+ax.y);
            } else if(EPI==3){
                float2 ax=*(const float2*)(aux+(size_t)(r&(Tt-1))*Nv+col);
                *(float2*)(outF+o)=make_float2(v0+ax.x, v1+ax.y);
            } else {
                *(float2*)(outF+o)=make_float2(v0,v1);
            }
        }
    }
}

// ---------- weight transpose + fp16: W[K,N] -> Wt[N,K] ----------
__global__ __launch_bounds__(256)
void trk(const float* __restrict__ W, __half* __restrict__ Wt, int K, int N)
{
    __shared__ float t[32][33];
    int n0=blockIdx.x*32, k0=blockIdx.y*32;
    int tx=threadIdx.x&31, ty=threadIdx.x>>5;
#pragma unroll
    for(int i=0;i<4;i++) t[ty+i*8][tx]=W[(size_t)(k0+ty+i*8)*N+n0+tx];
    __syncthreads();
#pragma unroll
    for(int i=0;i<4;i++)
        Wt[(size_t)(n0+ty+i*8)*K+k0+tx]=__float2half_rn(t[tx][ty+i*8]);
}

__global__ __launch_bounds__(256)
void cvth(const float* __restrict__ x, __half* __restrict__ o){
    size_t i=(size_t)blockIdx.x*256+threadIdx.x;
    o[i]=__float2half_rn(x[i]);
}

// ---------- LayerNorm (templated output: fp16 planes or fp32) ----------
template<bool F32OUT>
__global__ __launch_bounds__(256)
void ln_kernel(const float* __restrict__ x, const float* __restrict__ w,
               const float* __restrict__ b, __half* __restrict__ oh, float* __restrict__ of)
{
    int row=blockIdx.x;
    const float* xr=x+(size_t)row*Cc;
    float v[4], s=0.f, ss=0.f;
#pragma unroll
    for(int i=0;i<4;i++){ v[i]=xr[threadIdx.x+i*256]; s+=v[i]; ss+=v[i]*v[i]; }
#pragma unroll
    for(int off=16;off;off>>=1){ s+=__shfl_xor_sync(~0u,s,off); ss+=__shfl_xor_sync(~0u,ss,off); }
    __shared__ float red[16]; __shared__ float mean_s, rstd_s;
    int w8=threadIdx.x>>5;
    if((threadIdx.x&31)==0){ red[w8]=s; red[8+w8]=ss; }
    __syncthreads();
    if(threadIdx.x==0){
        float S=0.f,SS=0.f;
#pragma unroll
        for(int i=0;i<8;i++){ S+=red[i]; SS+=red[8+i]; }
        float m=S*(1.0f/Cc);
        mean_s=m; rstd_s=rsqrtf(SS*(1.0f/Cc)-m*m+LN_EPS);
    }
    __syncthreads();
    float m=mean_s, r=rstd_s;
    size_t rb=(size_t)row*Cc;
#pragma unroll
    for(int i=0;i<4;i++){
        int c=threadIdx.x+i*256;
        float y=(v[i]-m)*r*w[c]+b[c];
        if(F32OUT) of[rb+c]=y; else oh[rb+c]=__float2half_rn(y);
    }
}

// ---------- bucketed local attention -> ctx fp16 ----------
constexpr int ATTN_SMEM=(64*65+128*65+128*65+64*129)*4;

__global__ __launch_bounds__(256)
void attn_kernel(const float* __restrict__ qkv, __half* __restrict__ ch)
{
    extern __shared__ float sm[];
    float* q=sm; float* kc=q+64*65; float* vc=kc+128*65; float* s=vc+128*65;
    const int n=blockIdx.x, h=blockIdx.y, bb=blockIdx.z;
    const int tid=threadIdx.x;
    const size_t rowbase=(size_t)(bb*Tt+n*BSz);
    const float* base=qkv+rowbase*(3*Cc);
    const int hoff=h*HD;

    for(int e=tid;e<64*64;e+=256){ int i=e>>6,d=e&63; q[i*65+d]=base[(size_t)i*3072+hoff+d]; }
    for(int e=tid;e<128*64;e+=256){
        int j=e>>6,d=e&63; float kv,vv;
        if(j<64){
            if(n==0){ kv=0.f; vv=0.f; }
            else{ const float* pb=qkv+(rowbase-64+j)*3072; kv=pb[1024+hoff+d]; vv=pb[2048+hoff+d]; }
        } else {
            const float* cb=base+(size_t)(j-64)*3072; kv=cb[1024+hoff+d]; vv=cb[2048+hoff+d];
        }
        kc[j*65+d]=kv; vc[j*65+d]=vv;
    }
    __syncthreads();
    {
        int i=tid>>2, jq=tid&3;
        float acc[32];
#pragma unroll
        for(int jj=0;jj<32;jj++) acc[jj]=0.f;
#pragma unroll 4
        for(int d=0;d<64;d++){
            float qv=q[i*65+d];
#pragma unroll
            for(int jj=0;jj<32;jj++) acc[jj]+=qv*kc[(jq+jj*4)*65+d];
        }
#pragma unroll
        for(int jj=0;jj<32;jj++){
            int j=jq+jj*4;
            bool vis=(j<64)||((j-64)<=i);
            s[i*129+j]=vis?acc[jj]*ATT_SCALE:-1e30f;
        }
    }
    __syncthreads();
    if(tid<64){
        float mx=-1e30f;
        for(int j=0;j<128;j++) mx=fmaxf(mx,s[tid*129+j]);
        float sum=0.f;
        for(int j=0;j<128;j++){ float e=expf(s[tid*129+j]-mx); s[tid*129+j]=e; sum+=e; }
        float inv=1.0f/sum;
        for(int j=0;j<128;j++) s[tid*129+j]*=inv;
    }
    __syncthreads();
    {
        int i=tid>>2, dq=tid&3;
        float acc[16];
#pragma unroll
        for(int dd=0;dd<16;dd++) acc[dd]=0.f;
        for(int j=0;j<128;j++){
            float av=s[i*129+j];
#pragma unroll
            for(int dd=0;dd<16;dd++) acc[dd]+=av*vc[j*65+dq+dd*4];
        }
        size_t ob=(rowbase+i)*Cc+hoff;
#pragma unroll
        for(int dd=0;dd<16;dd++) ch[ob+dq+dd*4]=__float2half_rn(acc[dd]);
    }
}

// ---------- actor head: fp32 SIMT, block = 8 rows ----------
__global__ __launch_bounds__(256)
void actor_head(const float* __restrict__ hb, const float* __restrict__ aw,
                const float* __restrict__ ab, float* __restrict__ out)
{
    __shared__ float rows[8][1024];
    int r0=blockIdx.x*8;
    for(int e=threadIdx.x;e<8*1024;e+=256)
        rows[e>>10][e&1023]=hb[(size_t)(r0+(e>>10))*Cc+(e&1023)];
    __syncthreads();
    int a=threadIdx.x&63, rs=threadIdx.x>>6;     // rs: 0..3, two rows each
#pragma unroll
    for(int rr=0;rr<2;rr++){
        int r=rs*2+rr;
        float sum=0.f;
        for(int k=0;k<1024;k++) sum+=rows[r][k]*aw[k*64+a];
        out[(size_t)(r0+r)*64+a]=sum+ab[a];
    }
}

// ---------- critic head + logstd (fp32) ----------
__global__ __launch_bounds__(256)
void head_small(const float* __restrict__ hb, const float* __restrict__ cw,
                const float* __restrict__ cb, const float* __restrict__ lstd,
                float* __restrict__ out)
{
    int row=blockIdx.x*8+(threadIdx.x>>5);
    int lane=threadIdx.x&31;
    const float* hr=hb+(size_t)row*Cc;
    float sum=0.f;
#pragma unroll 8
    for(int k=lane;k<Cc;k+=32) sum+=hr[k]*cw[k];
#pragma unroll
    for(int off=16;off;off>>=1) sum+=__shfl_xor_sync(~0u,sum,off);
    if(lane==0) out[(size_t)Mm*Aa+Aa+row]=sum+cb[0];
    if(blockIdx.x==0 && threadIdx.x<Aa) out[(size_t)Mm*Aa+threadIdx.x]=lstd[threadIdx.x];
}

// ---------- launcher ----------
extern "C" void kernel_launch(void* const* d_in, const int* in_sizes, int n_in,
                              void* d_out, int out_size)
{
    const float* states=(const float*)d_in[0];
    const float* se_w=(const float*)d_in[1];  const float* se_b=(const float*)d_in[2];
    const float* pos =(const float*)d_in[3];
    const float* ln1w=(const float*)d_in[4];  const float* ln1b=(const float*)d_in[5];
    const float* qkvw=(const float*)d_in[6];  const float* qkvb=(const float*)d_in[7];
    const float* aow =(const float*)d_in[8];  const float* aob =(const float*)d_in[9];
    const float* ln2w=(const float*)d_in[10]; const float* ln2b=(const float*)d_in[11];
    const float* w1  =(const float*)d_in[12]; const float* b1  =(const float*)d_in[13];
    const float* w2  =(const float*)d_in[14]; const float* b2  =(const float*)d_in[15];
    const float* lnfw=(const float*)d_in[16]; const float* lnfb=(const float*)d_in[17];
    const float* actw=(const float*)d_in[18]; const float* actb=(const float*)d_in[19];
    const float* lstd=(const float*)d_in[20];
    const float* crw =(const float*)d_in[21]; const float* crb =(const float*)d_in[22];
    float* out=(float*)d_out;

    float *x,*qkv;
    __half *sh,*hh,*ch,*mh,*wh;
    cudaGetSymbolAddress((void**)&x,g_x);    cudaGetSymbolAddress((void**)&qkv,g_qkv);
    cudaGetSymbolAddress((void**)&sh,g_sh);  cudaGetSymbolAddress((void**)&hh,g_hh);
    cudaGetSymbolAddress((void**)&ch,g_ch);  cudaGetSymbolAddress((void**)&mh,g_mh);
    cudaGetSymbolAddress((void**)&wh,g_wh);

    cudaFuncSetAttribute(gemmh<0>, cudaFuncAttributeMaxDynamicSharedMemorySize, GSMEM);
    cudaFuncSetAttribute(gemmh<1>, cudaFuncAttributeMaxDynamicSharedMemorySize, GSMEM);
    cudaFuncSetAttribute(gemmh<2>, cudaFuncAttributeMaxDynamicSharedMemorySize, GSMEM);
    cudaFuncSetAttribute(gemmh<3>, cudaFuncAttributeMaxDynamicSharedMemorySize, GSMEM);
    cudaFuncSetAttribute(attn_kernel, cudaFuncAttributeMaxDynamicSharedMemorySize, ATTN_SMEM);

    // weight prep: transpose + fp16
    trk<<<dim3(1024/32,256/32),256>>>(se_w, wh+SE_OFF, 256,1024);
    for(int l=0;l<Ll;l++){
        trk<<<dim3(3072/32,1024/32),256>>>(qkvw+(size_t)l*QKV_SZ, wh+QKV_OFF+l*QKV_SZ, 1024,3072);
        trk<<<dim3(1024/32,1024/32),256>>>(aow +(size_t)l*AO_SZ,  wh+AO_OFF +l*AO_SZ,  1024,1024);
        trk<<<dim3(4096/32,1024/32),256>>>(w1  +(size_t)l*W1_SZ,  wh+W1_OFF +l*W1_SZ,  1024,4096);
        trk<<<dim3(1024/32,4096/32),256>>>(w2  +(size_t)l*W2_SZ,  wh+W2_OFF +l*W2_SZ,  4096,1024);
    }
    cvth<<<Mm*SD/256,256>>>(states, sh);

    const dim3 gC(8,Mm/128), g3C(24,Mm/128), g4C(32,Mm/128);

    // x = states @ se_w + se_b + pos
    gemmh<3><<<gC,256,GSMEM>>>(sh, wh+SE_OFF, se_b, pos, x, nullptr, 1024, 256);

    for(int l=0;l<Ll;l++){
        ln_kernel<false><<<Mm,256>>>(x, ln1w+l*Cc, ln1b+l*Cc, hh, nullptr);
        gemmh<0><<<g3C,256,GSMEM>>>(hh, wh+QKV_OFF+l*QKV_SZ, qkvb+(size_t)l*3072, nullptr, qkv, nullptr, 3072, 1024);
        attn_kernel<<<dim3(Tt/BSz,Hh,Bb),256,ATTN_SMEM>>>(qkv, ch);
        gemmh<2><<<gC,256,GSMEM>>>(ch, wh+AO_OFF+l*AO_SZ, aob+(size_t)l*1024, x, x, nullptr, 1024, 1024);
        ln_kernel<false><<<Mm,256>>>(x, ln2w+l*Cc, ln2b+l*Cc, hh, nullptr);
        gemmh<1><<<g4C,256,GSMEM>>>(hh, wh+W1_OFF+l*W1_SZ, b1+(size_t)l*4096, nullptr, nullptr, mh, 4096, 1024);
        gemmh<2><<<gC,256,GSMEM>>>(mh, wh+W2_OFF+l*W2_SZ, b2+(size_t)l*1024, x, x, nullptr, 1024, 4096);
    }

    // final LN -> fp32 (reuse qkv buffer), heads in fp32 SIMT
    ln_kernel<true><<<Mm,256>>>(x, lnfw, lnfb, nullptr, qkv);
    actor_head<<<Mm/8,256>>>(qkv, actw, actb, out);
    head_small<<<Mm/8,256>>>(qkv, crw, crb, lstd, out);
}

// round 13
// speedup vs baseline: 3.1026x; 1.0046x over previous
#include <cuda_runtime.h>
#include <cuda_fp16.h>
#include <cstdint>
#include <cmath>

constexpr int Bb=4, Tt=4096, SD=256, Cc=1024, Aa=64, Ll=6, Hh=16, BSz=64;
constexpr int Mm=Bb*Tt, HD=Cc/Hh;
constexpr float ATT_SCALE=0.125f, LN_EPS=1e-5f;

// transposed fp16 weights, packed (element offsets)
constexpr size_t SE_OFF=0;
constexpr size_t QKV_OFF=SE_OFF+1024UL*256, QKV_SZ=3072UL*1024;
constexpr size_t AO_OFF =QKV_OFF+6*QKV_SZ,  AO_SZ =1024UL*1024;
constexpr size_t W1_OFF =AO_OFF +6*AO_SZ,   W1_SZ =4096UL*1024;
constexpr size_t W2_OFF =W1_OFF +6*W1_SZ,   W2_SZ =1024UL*4096;
constexpr size_t WTOT   =W2_OFF +6*W2_SZ;

__device__ float g_x  [(size_t)Mm*Cc];       // residual stream (fp32)
__device__ float g_qkv[(size_t)Mm*3*Cc];     // qkv fp32 / final-LN fp32 reuse
__device__ __half g_sh[(size_t)Mm*SD];       // states fp16
__device__ __half g_hh[(size_t)Mm*Cc];       // LN out fp16
__device__ __half g_ch[(size_t)Mm*Cc];       // attn ctx fp16
__device__ __half g_mh[(size_t)Mm*4*Cc];     // mlp hidden fp16
__device__ __half g_wh[WTOT];                // weights fp16 [N][K]

// ---------- base-target PTX helpers ----------
__device__ __forceinline__ uint32_t smem_u32(const void* p){
    uint32_t a; asm("{ .reg .u64 t; cvta.to.shared.u64 t, %1; cvt.u32.u64 %0, t; }":"=r"(a):"l"(p)); return a;
}
__device__ __forceinline__ void cpa16(uint32_t dst, const void* src){
    asm volatile("cp.async.cg.shared.global [%0], [%1], 16;"::"r"(dst),"l"(src));
}
#define CP_COMMIT() asm volatile("cp.async.commit_group;":::"memory")
__device__ __forceinline__ void ldsm4(uint32_t* r, uint32_t a){
    asm volatile("ldmatrix.sync.aligned.m8n8.x4.shared.b16 {%0,%1,%2,%3}, [%4];"
        : "=r"(r[0]),"=r"(r[1]),"=r"(r[2]),"=r"(r[3]) : "r"(a));
}
__device__ __forceinline__ void mma16816(float* d, const uint32_t* a, const uint32_t* b){
    asm volatile("mma.sync.aligned.m16n8k16.row.col.f32.f16.f16.f32 "
        "{%0,%1,%2,%3}, {%4,%5,%6,%7}, {%8,%9}, {%0,%1,%2,%3};"
        : "+f"(d[0]),"+f"(d[1]),"+f"(d[2]),"+f"(d[3])
        : "r"(a[0]),"r"(a[1]),"r"(a[2]),"r"(a[3]), "r"(b[0]),"r"(b[1]));
}
__device__ __forceinline__ float gelu_exact(float x){
    return 0.5f*x*(1.0f+erff(x*0.70710678118654752f));
}

// ========== fp16 GEMM: out = EPI(A[M,K] @ Bt[N,K]^T + bias) ==========
// CTA tile 128(M) x 256(N), warp tile 64x64 (2x4 warps), K-step 32, 3-stage cp.async.
// smem row: 32 fp16 (64B) at 80B stride (conflict-free ldmatrix).
// NOTE: CP_COMMIT every iteration (even when no issue) — empty groups keep the
// wait_group accounting correct for the tail iterations. Conditional commit = race.
// EPI: 0 = fp32 out; 1 = gelu -> fp16; 2 = +aux residual fp32; 3 = +pos-embed fp32
constexpr int AOFF=0, BOFF=10240, STAGE=30720, GSMEM=3*STAGE;  // 92160 B

template<int EPI>
__global__ __launch_bounds__(256)
void gemmh(const __half* __restrict__ Ah, const __half* __restrict__ Bt,
           const float* __restrict__ bias, const float* __restrict__ aux,
           float* __restrict__ outF, __half* __restrict__ oH, int Nv, int K)
{
    extern __shared__ char smem[];
    const uint32_t sb = smem_u32(smem);
    const int tid=threadIdx.x, lane=tid&31, wid=tid>>5;
    const int wm=wid>>2, wn=wid&3;                 // 2 x 4 warps -> 64x64 tiles
    const int m0=blockIdx.y*128, n0=blockIdx.x*256;
    const int nk=K>>5;

    auto issue=[&](int buf,int k0){
        uint32_t ab=sb+buf*STAGE;
#pragma unroll
        for(int i=0;i<2;i++){                       // A: 128 rows x 4 chunks
            int c=tid+i*256;
            int r=c>>2, q=c&3;
            cpa16(ab+AOFF+r*80+q*16, Ah+(size_t)(m0+r)*K+k0+q*8);
        }
#pragma unroll
        for(int i=0;i<4;i++){                       // B: 256 rows x 4 chunks
            int c=tid+i*256;
            int r=c>>2, q=c&3;
            cpa16(ab+BOFF+r*80+q*16, Bt+(size_t)(n0+r)*K+k0+q*8);
        }
    };

    float acc[4][8][4];
#pragma unroll
    for(int a=0;a<4;a++)
#pragma unroll
    for(int b=0;b<8;b++)
#pragma unroll
    for(int c=0;c<4;c++) acc[a][b][c]=0.f;

    issue(0,0); CP_COMMIT();
    issue(1,32); CP_COMMIT();

    int buf=0;
    for(int s=0;s<nk;s++){
        asm volatile("cp.async.wait_group 1;":::"memory");
        __syncthreads();
        uint32_t ab=sb+buf*STAGE, bbs=ab+BOFF;
#pragma unroll
        for(int p=0;p<2;p++){
            uint32_t bfr[4][4];
#pragma unroll
            for(int ng=0;ng<4;ng++){
                uint32_t nrow=wn*64+ng*16+((lane>>4)&1)*8+(lane&7);
                uint32_t kby =((lane>>3)&1)*16+p*32;
                ldsm4(bfr[ng], bbs+nrow*80+kby);
            }
            uint32_t afr[4][4];
#pragma unroll
            for(int mt=0;mt<4;mt++){
                uint32_t row=wm*64+mt*16+((lane>>3)&1)*8+(lane&7);
                uint32_t kby=((lane>>4)&1)*16+p*32;
                ldsm4(afr[mt], ab+row*80+kby);
            }
#pragma unroll
            for(int mt=0;mt<4;mt++)
#pragma unroll
            for(int nt=0;nt<8;nt++)
                mma16816(acc[mt][nt], afr[mt], &bfr[nt>>1][(nt&1)*2]);
        }
        if(s+2<nk) issue((buf+2)%3,(s+2)*32);
        CP_COMMIT();                                 // unconditional — the fix
        buf=(buf+1)%3;
    }

    // ---- epilogue ----
#pragma unroll
    for(int mt=0;mt<4;mt++)
#pragma unroll
    for(int nt=0;nt<8;nt++){
        int col=n0+wn*64+nt*8+2*(lane&3);
        int r0=m0+wm*64+mt*16+(lane>>2);
        float2 bv=*(const float2*)(bias+col);
#pragma unroll
        for(int hrow=0;hrow<2;hrow++){
            int r=r0+hrow*8;
            float v0=acc[mt][nt][hrow*2+0]+bv.x;
            float v1=acc[mt][nt][hrow*2+1]+bv.y;
            size_t o=(size_t)r*Nv+col;
            if(EPI==1){
                v0=gelu_exact(v0); v1=gelu_exact(v1);
                __half2 hp; hp.x=__float2half_rn(v0); hp.y=__float2half_rn(v1);
                *(__half2*)(oH+o)=hp;
            } else if(EPI==2){
                float2 ax=*(const float2*)(aux+o);
                *(float2*)(outF+o)=make_float2(v0+ax.x, v1+ax.y);
            } else if(EPI==3){
                float2 ax=*(const float2*)(aux+(size_t)(r&(Tt-1))*Nv+col);
                *(float2*)(outF+o)=make_float2(v0+ax.x, v1+ax.y);
            } else {
                *(float2*)(outF+o)=make_float2(v0,v1);
            }
        }
    }
}

// ---------- weight transpose + fp16: W[K,N] -> Wt[N,K] ----------
__global__ __launch_bounds__(256)
void trk(const float* __restrict__ W, __half* __restrict__ Wt, int K, int N)
{
    __shared__ float t[32][33];
    int n0=blockIdx.x*32, k0=blockIdx.y*32;
    int tx=threadIdx.x&31, ty=threadIdx.x>>5;
#pragma unroll
    for(int i=0;i<4;i++) t[ty+i*8][tx]=W[(size_t)(k0+ty+i*8)*N+n0+tx];
    __syncthreads();
#pragma unroll
    for(int i=0;i<4;i++)
        Wt[(size_t)(n0+ty+i*8)*K+k0+tx]=__float2half_rn(t[tx][ty+i*8]);
}

__global__ __launch_bounds__(256)
void cvth(const float* __restrict__ x, __half* __restrict__ o){
    size_t i=(size_t)blockIdx.x*256+threadIdx.x;
    o[i]=__float2half_rn(x[i]);
}

// ---------- LayerNorm (templated output: fp16 or fp32) ----------
template<bool F32OUT>
__global__ __launch_bounds__(256)
void ln_kernel(const float* __restrict__ x, const float* __restrict__ w,
               const float* __restrict__ b, __half* __restrict__ oh, float* __restrict__ of)
{
    int row=blockIdx.x;
    const float* xr=x+(size_t)row*Cc;
    float v[4], s=0.f, ss=0.f;
#pragma unroll
    for(int i=0;i<4;i++){ v[i]=xr[threadIdx.x+i*256]; s+=v[i]; ss+=v[i]*v[i]; }
#pragma unroll
    for(int off=16;off;off>>=1){ s+=__shfl_xor_sync(~0u,s,off); ss+=__shfl_xor_sync(~0u,ss,off); }
    __shared__ float red[16]; __shared__ float mean_s, rstd_s;
    int w8=threadIdx.x>>5;
    if((threadIdx.x&31)==0){ red[w8]=s; red[8+w8]=ss; }
    __syncthreads();
    if(threadIdx.x==0){
        float S=0.f,SS=0.f;
#pragma unroll
        for(int i=0;i<8;i++){ S+=red[i]; SS+=red[8+i]; }
        float m=S*(1.0f/Cc);
        mean_s=m; rstd_s=rsqrtf(SS*(1.0f/Cc)-m*m+LN_EPS);
    }
    __syncthreads();
    float m=mean_s, r=rstd_s;
    size_t rb=(size_t)row*Cc;
#pragma unroll
    for(int i=0;i<4;i++){
        int c=threadIdx.x+i*256;
        float y=(v[i]-m)*r*w[c]+b[c];
        if(F32OUT) of[rb+c]=y; else oh[rb+c]=__float2half_rn(y);
    }
}

// ---------- bucketed local attention -> ctx fp16 ----------
constexpr int ATTN_SMEM=(64*65+128*65+128*65+64*129)*4;

__global__ __launch_bounds__(256)
void attn_kernel(const float* __restrict__ qkv, __half* __restrict__ ch)
{
    extern __shared__ float sm[];
    float* q=sm; float* kc=q+64*65; float* vc=kc+128*65; float* s=vc+128*65;
    const int n=blockIdx.x, h=blockIdx.y, bb=blockIdx.z;
    const int tid=threadIdx.x;
    const size_t rowbase=(size_t)(bb*Tt+n*BSz);
    const float* base=qkv+rowbase*(3*Cc);
    const int hoff=h*HD;

    for(int e=tid;e<64*64;e+=256){ int i=e>>6,d=e&63; q[i*65+d]=base[(size_t)i*3072+hoff+d]; }
    for(int e=tid;e<128*64;e+=256){
        int j=e>>6,d=e&63; float kv,vv;
        if(j<64){
            if(n==0){ kv=0.f; vv=0.f; }
            else{ const float* pb=qkv+(rowbase-64+j)*3072; kv=pb[1024+hoff+d]; vv=pb[2048+hoff+d]; }
        } else {
            const float* cb=base+(size_t)(j-64)*3072; kv=cb[1024+hoff+d]; vv=cb[2048+hoff+d];
        }
        kc[j*65+d]=kv; vc[j*65+d]=vv;
    }
    __syncthreads();
    {
        int i=tid>>2, jq=tid&3;
        float acc[32];
#pragma unroll
        for(int jj=0;jj<32;jj++) acc[jj]=0.f;
#pragma unroll 4
        for(int d=0;d<64;d++){
            float qv=q[i*65+d];
#pragma unroll
            for(int jj=0;jj<32;jj++) acc[jj]+=qv*kc[(jq+jj*4)*65+d];
        }
#pragma unroll
        for(int jj=0;jj<32;jj++){
            int j=jq+jj*4;
            bool vis=(j<64)||((j-64)<=i);
            s[i*129+j]=vis?acc[jj]*ATT_SCALE:-1e30f;
        }
    }
    __syncthreads();
    if(tid<64){
        float mx=-1e30f;
        for(int j=0;j<128;j++) mx=fmaxf(mx,s[tid*129+j]);
        float sum=0.f;
        for(int j=0;j<128;j++){ float e=expf(s[tid*129+j]-mx); s[tid*129+j]=e; sum+=e; }
        float inv=1.0f/sum;
        for(int j=0;j<128;j++) s[tid*129+j]*=inv;
    }
    __syncthreads();
    {
        int i=tid>>2, dq=tid&3;
        float acc[16];
#pragma unroll
        for(int dd=0;dd<16;dd++) acc[dd]=0.f;
        for(int j=0;j<128;j++){
            float av=s[i*129+j];
#pragma unroll
            for(int dd=0;dd<16;dd++) acc[dd]+=av*vc[j*65+dq+dd*4];
        }
        size_t ob=(rowbase+i)*Cc+hoff;
#pragma unroll
        for(int dd=0;dd<16;dd++) ch[ob+dq+dd*4]=__float2half_rn(acc[dd]);
    }
}

// ---------- actor head: fp32 SIMT, block = 8 rows ----------
__global__ __launch_bounds__(256)
void actor_head(const float* __restrict__ hb, const float* __restrict__ aw,
                const float* __restrict__ ab, float* __restrict__ out)
{
    __shared__ float rows[8][1024];
    int r0=blockIdx.x*8;
    for(int e=threadIdx.x;e<8*1024;e+=256)
        rows[e>>10][e&1023]=hb[(size_t)(r0+(e>>10))*Cc+(e&1023)];
    __syncthreads();
    int a=threadIdx.x&63, rs=threadIdx.x>>6;
#pragma unroll
    for(int rr=0;rr<2;rr++){
        int r=rs*2+rr;
        float sum=0.f;
        for(int k=0;k<1024;k++) sum+=rows[r][k]*aw[k*64+a];
        out[(size_t)(r0+r)*64+a]=sum+ab[a];
    }
}

// ---------- critic head + logstd (fp32) ----------
__global__ __launch_bounds__(256)
void head_small(const float* __restrict__ hb, const float* __restrict__ cw,
                const float* __restrict__ cb, const float* __restrict__ lstd,
                float* __restrict__ out)
{
    int row=blockIdx.x*8+(threadIdx.x>>5);
    int lane=threadIdx.x&31;
    const float* hr=hb+(size_t)row*Cc;
    float sum=0.f;
#pragma unroll 8
    for(int k=lane;k<Cc;k+=32) sum+=hr[k]*cw[k];
#pragma unroll
    for(int off=16;off;off>>=1) sum+=__shfl_xor_sync(~0u,sum,off);
    if(lane==0) out[(size_t)Mm*Aa+Aa+row]=sum+cb[0];
    if(blockIdx.x==0 && threadIdx.x<Aa) out[(size_t)Mm*Aa+threadIdx.x]=lstd[threadIdx.x];
}

// ---------- launcher ----------
extern "C" void kernel_launch(void* const* d_in, const int* in_sizes, int n_in,
                              void* d_out, int out_size)
{
    const float* states=(const float*)d_in[0];
    const float* se_w=(const float*)d_in[1];  const float* se_b=(const float*)d_in[2];
    const float* pos =(const float*)d_in[3];
    const float* ln1w=(const float*)d_in[4];  const float* ln1b=(const float*)d_in[5];
    const float* qkvw=(const float*)d_in[6];  const float* qkvb=(const float*)d_in[7];
    const float* aow =(const float*)d_in[8];  const float* aob =(const float*)d_in[9];
    const float* ln2w=(const float*)d_in[10]; const float* ln2b=(const float*)d_in[11];
    const float* w1  =(const float*)d_in[12]; const float* b1  =(const float*)d_in[13];
    const float* w2  =(const float*)d_in[14]; const float* b2  =(const float*)d_in[15];
    const float* lnfw=(const float*)d_in[16]; const float* lnfb=(const float*)d_in[17];
    const float* actw=(const float*)d_in[18]; const float* actb=(const float*)d_in[19];
    const float* lstd=(const float*)d_in[20];
    const float* crw =(const float*)d_in[21]; const float* crb =(const float*)d_in[22];
    float* out=(float*)d_out;

    float *x,*qkv;
    __half *sh,*hh,*ch,*mh,*wh;
    cudaGetSymbolAddress((void**)&x,g_x);    cudaGetSymbolAddress((void**)&qkv,g_qkv);
    cudaGetSymbolAddress((void**)&sh,g_sh);  cudaGetSymbolAddress((void**)&hh,g_hh);
    cudaGetSymbolAddress((void**)&ch,g_ch);  cudaGetSymbolAddress((void**)&mh,g_mh);
    cudaGetSymbolAddress((void**)&wh,g_wh);

    cudaFuncSetAttribute(gemmh<0>, cudaFuncAttributeMaxDynamicSharedMemorySize, GSMEM);
    cudaFuncSetAttribute(gemmh<1>, cudaFuncAttributeMaxDynamicSharedMemorySize, GSMEM);
    cudaFuncSetAttribute(gemmh<2>, cudaFuncAttributeMaxDynamicSharedMemorySize, GSMEM);
    cudaFuncSetAttribute(gemmh<3>, cudaFuncAttributeMaxDynamicSharedMemorySize, GSMEM);
    cudaFuncSetAttribute(attn_kernel, cudaFuncAttributeMaxDynamicSharedMemorySize, ATTN_SMEM);

    const dim3 gC(4,Mm/128), g3C(12,Mm/128), g4C(16,Mm/128);

    // launch order keeps the layer-0 QKV GEMM at launch index 6 (ncu -s 5 -c 1 captures it)
    trk<<<dim3(1024/32,256/32),256>>>(se_w, wh+SE_OFF, 256,1024);               // 1
    cvth<<<Mm*SD/256,256>>>(states, sh);                                         // 2
    gemmh<3><<<gC,256,GSMEM>>>(sh, wh+SE_OFF, se_b, pos, x, nullptr, 1024,256);  // 3

    for(int l=0;l<Ll;l++){
        ln_kernel<false><<<Mm,256>>>(x, ln1w+l*Cc, ln1b+l*Cc, hh, nullptr);      // 4
        trk<<<dim3(3072/32,1024/32),256>>>(qkvw+(size_t)l*QKV_SZ, wh+QKV_OFF+l*QKV_SZ, 1024,3072); // 5
        gemmh<0><<<g3C,256,GSMEM>>>(hh, wh+QKV_OFF+l*QKV_SZ, qkvb+(size_t)l*3072, nullptr, qkv, nullptr, 3072,1024); // 6 <- profiled
        attn_kernel<<<dim3(Tt/BSz,Hh,Bb),256,ATTN_SMEM>>>(qkv, ch);
        trk<<<dim3(1024/32,1024/32),256>>>(aow+(size_t)l*AO_SZ, wh+AO_OFF+l*AO_SZ, 1024,1024);
        gemmh<2><<<gC,256,GSMEM>>>(ch, wh+AO_OFF+l*AO_SZ, aob+(size_t)l*1024, x, x, nullptr, 1024,1024);
        ln_kernel<false><<<Mm,256>>>(x, ln2w+l*Cc, ln2b+l*Cc, hh, nullptr);
        trk<<<dim3(4096/32,1024/32),256>>>(w1+(size_t)l*W1_SZ, wh+W1_OFF+l*W1_SZ, 1024,4096);
        gemmh<1><<<g4C,256,GSMEM>>>(hh, wh+W1_OFF+l*W1_SZ, b1+(size_t)l*4096, nullptr, nullptr, mh, 4096,1024);
        trk<<<dim3(1024/32,4096/32),256>>>(w2+(size_t)l*W2_SZ, wh+W2_OFF+l*W2_SZ, 4096,1024);
        gemmh<2><<<gC,256,GSMEM>>>(mh, wh+W2_OFF+l*W2_SZ, b2+(size_t)l*1024, x, x, nullptr, 1024,4096);
    }

    // final LN -> fp32 (reuse qkv buffer), heads in fp32 SIMT
    ln_kernel<true><<<Mm,256>>>(x, lnfw, lnfb, nullptr, qkv);
    actor_head<<<Mm/8,256>>>(qkv, actw, actb, out);
    head_small<<<Mm/8,256>>>(qkv, crw, crb, lstd, out);
}